// round 15
// baseline (speedup 1.0000x reference)
#include <cuda_runtime.h>
#include <cuda_fp16.h>
#include <math.h>
#include <stdint.h>

#define BQ   8192
#define DIN  1024
#define NEXP 8
#define DEXP 1024

// GEMM tiling: BM=128, BN=128, BK=64, 512 threads / 16 warps (warp tile
// 32x32), 3-stage cp.async pipeline, 2 CTAs per SM -> 32 warps/SM.
#define BK        64
#define NCHUNK    16                  // 1024 / BK
#define ROWB      144                 // SMEM row stride bytes (64 fp16 + 16 pad)
#define ARR_B     (128 * ROWB)        // 18432 B per array
#define STAGE_B   (2 * ARR_B)         // Ah | Bh = 36864 B
#define NSTAGE    3
#define TOK_OFF   (NSTAGE * STAGE_B)  // 110592
#define SMEM_T    (TOK_OFF + 2048)

// ---------------------------------------------------------------------------
// Static device scratch (sanctioned no-alloc path)
// ---------------------------------------------------------------------------
__device__ int   g_cnt[NEXP];
__device__ int   g_tok[NEXP * BQ];
__device__ float g_wt [NEXP * BQ];
__device__ __align__(256) __half g_xh [(size_t)BQ * DIN];
__device__ __align__(256) __half g_w1h[(size_t)NEXP * DIN * DEXP];
__device__ __align__(256) __half g_w2h[(size_t)NEXP * DEXP * DEXP];
__device__ __align__(256) __half g_hh [(size_t)NEXP * BQ * DEXP];

// ---------------------------------------------------------------------------
// PTX helpers (sm_103-base-target safe: mma.sync / ldmatrix / cp.async only)
// ---------------------------------------------------------------------------
__device__ __forceinline__ uint32_t smem_u32(const void* p) {
    uint32_t a;
    asm("{ .reg .u64 t; cvta.to.shared.u64 t, %1; cvt.u32.u64 %0, t; }"
        : "=r"(a) : "l"(p));
    return a;
}
#define CPASYNC(dst, src) \
    asm volatile("cp.async.cg.shared.global [%0], [%1], 16;" \
                 :: "r"(dst), "l"(src) : "memory")
#define CPCOMMIT()  asm volatile("cp.async.commit_group;" ::: "memory")
#define CPWAIT1()   asm volatile("cp.async.wait_group 1;" ::: "memory")
#define CPWAIT0()   asm volatile("cp.async.wait_group 0;" ::: "memory")

__device__ __forceinline__ void ldm4(uint32_t* r, uint32_t addr) {
    asm volatile("ldmatrix.sync.aligned.m8n8.x4.shared.b16 {%0,%1,%2,%3}, [%4];"
                 : "=r"(r[0]), "=r"(r[1]), "=r"(r[2]), "=r"(r[3]) : "r"(addr));
}
__device__ __forceinline__ void mma_f16(float* d, const uint32_t* a, const uint32_t* b) {
    asm volatile(
        "mma.sync.aligned.m16n8k16.row.col.f32.f16.f16.f32 "
        "{%0,%1,%2,%3}, {%4,%5,%6,%7}, {%8,%9}, {%0,%1,%2,%3};"
        : "+f"(d[0]), "+f"(d[1]), "+f"(d[2]), "+f"(d[3])
        : "r"(a[0]), "r"(a[1]), "r"(a[2]), "r"(a[3]), "r"(b[0]), "r"(b[1]));
}

// ---------------------------------------------------------------------------
// Kernel: zero the MoE output region and the routing counters
// ---------------------------------------------------------------------------
__global__ __launch_bounds__(256)
void init_kernel(float* __restrict__ out) {
    int i = blockIdx.x * 256 + threadIdx.x;
    if (i < (BQ * DEXP) / 4)
        ((float4*)out)[i] = make_float4(0.f, 0.f, 0.f, 0.f);
    if (i < NEXP) g_cnt[i] = 0;
}

// ---------------------------------------------------------------------------
// Kernel: gating (logits, top-2, softmax, routing)
// ---------------------------------------------------------------------------
__global__ __launch_bounds__(256)
void gate_kernel(const float* __restrict__ x, const float* __restrict__ gw,
                 float* __restrict__ gate_out) {
    const int b   = blockIdx.x;
    const int tid = threadIdx.x;
    const float* xr = x + (size_t)b * DIN;

    float acc[8];
#pragma unroll
    for (int e = 0; e < 8; e++) acc[e] = 0.0f;
    for (int k = tid; k < DIN; k += 256) {
        float xv = xr[k];
        float4 g0 = *(const float4*)(gw + k * 8);
        float4 g1 = *(const float4*)(gw + k * 8 + 4);
        acc[0] += xv * g0.x; acc[1] += xv * g0.y;
        acc[2] += xv * g0.z; acc[3] += xv * g0.w;
        acc[4] += xv * g1.x; acc[5] += xv * g1.y;
        acc[6] += xv * g1.z; acc[7] += xv * g1.w;
    }
#pragma unroll
    for (int e = 0; e < 8; e++)
#pragma unroll
        for (int off = 16; off > 0; off >>= 1)
            acc[e] += __shfl_down_sync(0xffffffffu, acc[e], off);

    __shared__ float wpart[8][8];
    __shared__ float logits[8];
    __shared__ float sw[2];
    __shared__ int   si[2];
    const int warp = tid >> 5, lane = tid & 31;
    if (lane == 0)
#pragma unroll
        for (int e = 0; e < 8; e++) wpart[warp][e] = acc[e];
    __syncthreads();
    if (tid < 8) {
        float s = 0.0f;
#pragma unroll
        for (int w = 0; w < 8; w++) s += wpart[w][tid];
        logits[tid] = s;
    }
    __syncthreads();

    if (tid == 0) {
        int i0 = 0; float v0 = logits[0];
#pragma unroll
        for (int e = 1; e < 8; e++) if (logits[e] > v0) { v0 = logits[e]; i0 = e; }
        int i1 = -1; float v1 = -3.4e38f;
#pragma unroll
        for (int e = 0; e < 8; e++)
            if (e != i0 && logits[e] > v1) { v1 = logits[e]; i1 = e; }
        float ex  = expf(v1 - v0);
        float inv = 1.0f / (1.0f + ex);
        float w0 = inv, w1 = ex * inv;
        si[0] = i0; si[1] = i1; sw[0] = w0; sw[1] = w1;
        int p0 = atomicAdd(&g_cnt[i0], 1);
        g_tok[i0 * BQ + p0] = b; g_wt[i0 * BQ + p0] = w0;
        int p1 = atomicAdd(&g_cnt[i1], 1);
        g_tok[i1 * BQ + p1] = b; g_wt[i1 * BQ + p1] = w1;
    }
    __syncthreads();
    if (tid < 8) {
        float v = (tid == si[0]) ? sw[0] : ((tid == si[1]) ? sw[1] : 0.0f);
        gate_out[(size_t)b * 8 + tid] = v;
    }
}

// ---------------------------------------------------------------------------
// Kernel: round x to fp16
// ---------------------------------------------------------------------------
__global__ __launch_bounds__(256)
void convert_x_kernel(const float* __restrict__ x) {
    size_t i = ((size_t)blockIdx.x * 256 + threadIdx.x) * 4;
    float4 v = *(const float4*)(x + i);
    uint2 hp;
    hp.x = (uint32_t)__half_as_ushort(__float2half_rn(v.x))
         | ((uint32_t)__half_as_ushort(__float2half_rn(v.y)) << 16);
    hp.y = (uint32_t)__half_as_ushort(__float2half_rn(v.z))
         | ((uint32_t)__half_as_ushort(__float2half_rn(v.w)) << 16);
    *(uint2*)(g_xh + i) = hp;
}

// ---------------------------------------------------------------------------
// Kernel: transpose w1/w2 -> [e][n][k] fp16
// ---------------------------------------------------------------------------
__global__ void convert_w_kernel(const float* __restrict__ w1,
                                 const float* __restrict__ w2) {
    __shared__ float t[32][33];
    const int z = blockIdx.z;
    const float* src = (z < 8 ? w1 : w2) + (size_t)(z & 7) * DIN * DEXP;
    __half* dh = (z < 8 ? g_w1h : g_w2h) + (size_t)(z & 7) * DIN * DEXP;
    const int n0 = blockIdx.x * 32, k0 = blockIdx.y * 32;
    const int tx = threadIdx.x, ty = threadIdx.y;
#pragma unroll
    for (int j = 0; j < 32; j += 8)
        t[ty + j][tx] = src[(size_t)(k0 + ty + j) * DEXP + n0 + tx];
    __syncthreads();
#pragma unroll
    for (int j = 0; j < 32; j += 8) {
        size_t o = (size_t)(n0 + ty + j) * DIN + k0 + tx;
        dh[o] = __float2half_rn(t[tx][ty + j]);
    }
}

// ---------------------------------------------------------------------------
// fp16 mma.sync GEMMs. 512 threads / 16 warps: warp grid 4x4, warp tile
// 32x32 (acc 32 regs). 2 CTAs/SM -> 8 warps per SMSP for latency hiding.
// grid: x = e*64 + m_tile (early exit), y = n_tile (8).
// ---------------------------------------------------------------------------
struct FragPtrs { const __half *ah, *bh; };

// 512 threads: thread -> row (tid>>2), TWO 16B segs ((tid&3)*2, +1).
// Coverage: 512 threads x 2 segs x 16 B = 16384 B = full 128x128B array.
__device__ __forceinline__ void load_stage(uint32_t st, const FragPtrs& p,
                                           int k0, uint32_t so) {
    CPASYNC(st + so,              p.ah + k0);
    CPASYNC(st + so + 16,         p.ah + k0 + 8);
    CPASYNC(st + ARR_B + so,      p.bh + k0);
    CPASYNC(st + ARR_B + so + 16, p.bh + k0 + 8);
    CPCOMMIT();
}

__device__ __forceinline__ void compute_chunk(uint32_t st, uint32_t aoff,
                                              uint32_t boff, float acc[2][4][4]) {
#pragma unroll
    for (int kk = 0; kk < 4; ++kk) {
        uint32_t ah[2][4], bh[2][4];
#pragma unroll
        for (int i = 0; i < 2; ++i)
            ldm4(ah[i], st + aoff + i * (16 * ROWB) + kk * 32);
#pragma unroll
        for (int pp = 0; pp < 2; ++pp)
            ldm4(bh[pp], st + ARR_B + boff + pp * (16 * ROWB) + kk * 32);
#pragma unroll
        for (int i = 0; i < 2; ++i)
#pragma unroll
            for (int nt = 0; nt < 4; ++nt)
                mma_f16(acc[i][nt], ah[i], &bh[nt >> 1][(nt & 1) * 2]);
    }
}

// Two barriers per chunk (write/read phase split; proven neutral-to-best).
__device__ __forceinline__ void run_mainloop(uint32_t sbase, const FragPtrs& p,
                                             uint32_t so,
                                             uint32_t aoff, uint32_t boff,
                                             float acc[2][4][4]) {
#pragma unroll
    for (int s = 0; s < NSTAGE - 1; ++s)
        load_stage(sbase + s * STAGE_B, p, s * BK, so);
#pragma unroll 1
    for (int c = 0; c < NCHUNK; ++c) {
        if (c + NSTAGE - 1 < NCHUNK) CPWAIT1(); else CPWAIT0();
        __syncthreads();
        if (c + NSTAGE - 1 < NCHUNK)
            load_stage(sbase + ((c + NSTAGE - 1) % NSTAGE) * STAGE_B, p,
                       (c + NSTAGE - 1) * BK, so);
        compute_chunk(sbase + (c % NSTAGE) * STAGE_B, aoff, boff, acc);
        __syncthreads();
    }
}

__global__ __launch_bounds__(512, 2)
void gemm1_mma(const float* __restrict__ b1) {
    extern __shared__ char sm[];
    const int e    = blockIdx.x >> 6;
    const int tm   = blockIdx.x & 63;
    const int cnt  = g_cnt[e];
    const int row0 = tm * 128;
    if (row0 >= cnt) return;
    const int n0  = blockIdx.y * 128;
    const int tid = threadIdx.x;
    const int wid = tid >> 5, lane = tid & 31;
    const int wm = wid >> 2, wn = wid & 3;

    const uint32_t sbase = smem_u32(sm);
    int* tok_s = (int*)(sm + TOK_OFF);
    if (tid < 128) {
        int r = row0 + tid;
        tok_s[tid] = (r < cnt) ? g_tok[e * BQ + r] : g_tok[e * BQ + row0];
    }
    __syncthreads();

    // loader map: row = tid>>2, element offset = (tid&3)*16 fp16 (two 16B segs)
    const int crow = tid >> 2, ce0 = (tid & 3) * 16;
    const uint32_t so = crow * ROWB + ce0 * 2;
    FragPtrs p;
    p.ah = g_xh  + (size_t)tok_s[crow] * DIN + ce0;
    p.bh = g_w1h + ((size_t)e * DEXP + n0 + crow) * DIN + ce0;

    const uint32_t aoff = (wm * 32 + (lane & 15)) * ROWB + (lane >> 4) * 16;
    const uint32_t boff = (wn * 32 + ((lane >> 4) << 3) + (lane & 7)) * ROWB
                        + ((lane >> 3) & 1) * 16;

    float acc[2][4][4];
#pragma unroll
    for (int i = 0; i < 2; ++i)
#pragma unroll
        for (int j = 0; j < 4; ++j)
#pragma unroll
            for (int q = 0; q < 4; ++q) acc[i][j][q] = 0.0f;

    run_mainloop(sbase, p, so, aoff, boff, acc);

    // epilogue: bias + exact gelu -> fp16 h
    float bias[4][2];
#pragma unroll
    for (int nt = 0; nt < 4; ++nt) {
        int c0 = n0 + wn * 32 + nt * 8 + (lane & 3) * 2;
        bias[nt][0] = b1[e * DEXP + c0];
        bias[nt][1] = b1[e * DEXP + c0 + 1];
    }
#pragma unroll
    for (int i = 0; i < 2; ++i) {
#pragma unroll
        for (int half = 0; half < 2; ++half) {
            int r = wm * 32 + i * 16 + (lane >> 2) + half * 8;
            if (row0 + r >= cnt) continue;
            size_t rowbase = ((size_t)e * BQ + row0 + r) * DEXP;
#pragma unroll
            for (int nt = 0; nt < 4; ++nt) {
                int c0 = n0 + wn * 32 + nt * 8 + (lane & 3) * 2;
                float z0 = acc[i][nt][half * 2]     + bias[nt][0];
                float z1 = acc[i][nt][half * 2 + 1] + bias[nt][1];
                float gl0 = 0.5f * z0 * (1.0f + erff(z0 * 0.70710678118654752f));
                float gl1 = 0.5f * z1 * (1.0f + erff(z1 * 0.70710678118654752f));
                uint32_t hw = (uint32_t)__half_as_ushort(__float2half_rn(gl0))
                            | ((uint32_t)__half_as_ushort(__float2half_rn(gl1)) << 16);
                *(uint32_t*)(g_hh + rowbase + c0) = hw;
            }
        }
    }
}

__global__ __launch_bounds__(512, 2)
void gemm2_mma(const float* __restrict__ b2, float* __restrict__ out) {
    extern __shared__ char sm[];
    const int e    = blockIdx.x >> 6;
    const int tm   = blockIdx.x & 63;
    const int cnt  = g_cnt[e];
    const int row0 = tm * 128;
    if (row0 >= cnt) return;
    const int n0  = blockIdx.y * 128;
    const int tid = threadIdx.x;
    const int wid = tid >> 5, lane = tid & 31;
    const int wm = wid >> 2, wn = wid & 3;

    const uint32_t sbase = smem_u32(sm);
    int*   tok_s = (int*)(sm + TOK_OFF);
    float* wt_s  = (float*)(sm + TOK_OFF + 512);
    if (tid < 128) {
        int r = row0 + tid;
        if (r < cnt) { tok_s[tid] = g_tok[e * BQ + r]; wt_s[tid] = g_wt[e * BQ + r]; }
        else         { tok_s[tid] = 0;                 wt_s[tid] = 0.0f; }
    }
    __syncthreads();

    const int crow = tid >> 2, ce0 = (tid & 3) * 16;
    const uint32_t so = crow * ROWB + ce0 * 2;
    FragPtrs p;
    p.ah = g_hh  + ((size_t)e * BQ + row0 + crow) * DEXP + ce0;
    p.bh = g_w2h + ((size_t)e * DEXP + n0 + crow) * DEXP + ce0;

    const uint32_t aoff = (wm * 32 + (lane & 15)) * ROWB + (lane >> 4) * 16;
    const uint32_t boff = (wn * 32 + ((lane >> 4) << 3) + (lane & 7)) * ROWB
                        + ((lane >> 3) & 1) * 16;

    float acc[2][4][4];
#pragma unroll
    for (int i = 0; i < 2; ++i)
#pragma unroll
        for (int j = 0; j < 4; ++j)
#pragma unroll
            for (int q = 0; q < 4; ++q) acc[i][j][q] = 0.0f;

    run_mainloop(sbase, p, so, aoff, boff, acc);

    // epilogue: gate_w * (acc + bias) -> atomicAdd into out (2 deterministic
    // commutative fp32 adds per element onto zeroed buffer)
    float bias[4][2];
#pragma unroll
    for (int nt = 0; nt < 4; ++nt) {
        int c0 = n0 + wn * 32 + nt * 8 + (lane & 3) * 2;
        bias[nt][0] = b2[e * DEXP + c0];
        bias[nt][1] = b2[e * DEXP + c0 + 1];
    }
#pragma unroll
    for (int i = 0; i < 2; ++i) {
#pragma unroll
        for (int half = 0; half < 2; ++half) {
            int r = wm * 32 + i * 16 + (lane >> 2) + half * 8;
            if (row0 + r >= cnt) continue;
            float wgt = wt_s[r];
            float* orow = out + (size_t)tok_s[r] * DEXP;
#pragma unroll
            for (int nt = 0; nt < 4; ++nt) {
                int c0 = n0 + wn * 32 + nt * 8 + (lane & 3) * 2;
                atomicAdd(&orow[c0],     wgt * (acc[i][nt][half * 2]     + bias[nt][0]));
                atomicAdd(&orow[c0 + 1], wgt * (acc[i][nt][half * 2 + 1] + bias[nt][1]));
            }
        }
    }
}

// ---------------------------------------------------------------------------
// Launch: output = [moe_output (B*DEXP) | gate_weights (B*NEXP)]
// ---------------------------------------------------------------------------
extern "C" void kernel_launch(void* const* d_in, const int* in_sizes, int n_in,
                              void* d_out, int out_size) {
    const float* x  = (const float*)d_in[0];
    const float* gw = (const float*)d_in[1];
    const float* w1 = (const float*)d_in[2];
    const float* b1 = (const float*)d_in[3];
    const float* w2 = (const float*)d_in[4];
    const float* b2 = (const float*)d_in[5];
    float* out      = (float*)d_out;
    float* gate_out = out + (size_t)BQ * DEXP;

    cudaFuncSetAttribute(gemm1_mma, cudaFuncAttributeMaxDynamicSharedMemorySize, SMEM_T);
    cudaFuncSetAttribute(gemm2_mma, cudaFuncAttributeMaxDynamicSharedMemorySize, SMEM_T);

    init_kernel<<<(BQ * DEXP / 4 + 255) / 256, 256>>>(out);
    gate_kernel<<<BQ, 256>>>(x, gw, gate_out);
    convert_x_kernel<<<(BQ * DIN) / (256 * 4), 256>>>(x);
    convert_w_kernel<<<dim3(32, 32, 16), dim3(32, 8)>>>(w1, w2);

    dim3 grid(NEXP * (BQ / 128), DEXP / 128);
    gemm1_mma<<<grid, 512, SMEM_T>>>(b1);
    gemm2_mma<<<grid, 512, SMEM_T>>>(b2, out);
}

// round 16
// speedup vs baseline: 1.2694x; 1.2694x over previous
#include <cuda_runtime.h>
#include <cuda_fp16.h>
#include <math.h>
#include <stdint.h>

#define BQ   8192
#define DIN  1024
#define NEXP 8
#define DEXP 1024

// GEMM tiling: BM=128, BN=128, BK=64, 256 threads / 8 warps (warp tile 64x32),
// 3-stage cp.async pipeline, 2 CTAs per SM.  (Proven R10 configuration.)
#define BK        64
#define NCHUNK    16                  // 1024 / BK
#define ROWB      144                 // SMEM row stride bytes (64 fp16 + 16 pad)
#define ARR_B     (128 * ROWB)        // 18432 B per array
#define STAGE_B   (2 * ARR_B)         // Ah | Bh = 36864 B
#define NSTAGE    3
#define TOK_OFF   (NSTAGE * STAGE_B)  // 110592
#define SMEM_T    (TOK_OFF + 2048)

// ---------------------------------------------------------------------------
// Static device scratch (sanctioned no-alloc path)
// ---------------------------------------------------------------------------
__device__ int   g_cnt[NEXP];
__device__ int   g_tok[NEXP * BQ];
__device__ float g_wt [NEXP * BQ];
__device__ __align__(256) __half g_xh [(size_t)BQ * DIN];
__device__ __align__(256) __half g_w1h[(size_t)NEXP * DIN * DEXP];
__device__ __align__(256) __half g_w2h[(size_t)NEXP * DEXP * DEXP];
__device__ __align__(256) __half g_hh [(size_t)NEXP * BQ * DEXP];

// ---------------------------------------------------------------------------
// PTX helpers (sm_103-base-target safe: mma.sync / ldmatrix / cp.async only)
// ---------------------------------------------------------------------------
__device__ __forceinline__ uint32_t smem_u32(const void* p) {
    uint32_t a;
    asm("{ .reg .u64 t; cvta.to.shared.u64 t, %1; cvt.u32.u64 %0, t; }"
        : "=r"(a) : "l"(p));
    return a;
}
#define CPASYNC(dst, src) \
    asm volatile("cp.async.cg.shared.global [%0], [%1], 16;" \
                 :: "r"(dst), "l"(src) : "memory")
#define CPCOMMIT()  asm volatile("cp.async.commit_group;" ::: "memory")
#define CPWAIT1()   asm volatile("cp.async.wait_group 1;" ::: "memory")
#define CPWAIT0()   asm volatile("cp.async.wait_group 0;" ::: "memory")

__device__ __forceinline__ void ldm4(uint32_t* r, uint32_t addr) {
    asm volatile("ldmatrix.sync.aligned.m8n8.x4.shared.b16 {%0,%1,%2,%3}, [%4];"
                 : "=r"(r[0]), "=r"(r[1]), "=r"(r[2]), "=r"(r[3]) : "r"(addr));
}
__device__ __forceinline__ void mma_f16(float* d, const uint32_t* a, const uint32_t* b) {
    asm volatile(
        "mma.sync.aligned.m16n8k16.row.col.f32.f16.f16.f32 "
        "{%0,%1,%2,%3}, {%4,%5,%6,%7}, {%8,%9}, {%0,%1,%2,%3};"
        : "+f"(d[0]), "+f"(d[1]), "+f"(d[2]), "+f"(d[3])
        : "r"(a[0]), "r"(a[1]), "r"(a[2]), "r"(a[3]), "r"(b[0]), "r"(b[1]));
}

// ---------------------------------------------------------------------------
// Kernel: zero the MoE output region and the routing counters (vectorized)
// ---------------------------------------------------------------------------
__global__ __launch_bounds__(256)
void init_kernel(float* __restrict__ out) {
    int i = blockIdx.x * 256 + threadIdx.x;
    if (i < (BQ * DEXP) / 4)
        ((float4*)out)[i] = make_float4(0.f, 0.f, 0.f, 0.f);
    if (i < NEXP) g_cnt[i] = 0;
}

// ---------------------------------------------------------------------------
// Kernel: gating (logits, top-2, softmax, routing)
// ---------------------------------------------------------------------------
__global__ __launch_bounds__(256)
void gate_kernel(const float* __restrict__ x, const float* __restrict__ gw,
                 float* __restrict__ gate_out) {
    const int b   = blockIdx.x;
    const int tid = threadIdx.x;
    const float* xr = x + (size_t)b * DIN;

    float acc[8];
#pragma unroll
    for (int e = 0; e < 8; e++) acc[e] = 0.0f;
    for (int k = tid; k < DIN; k += 256) {
        float xv = xr[k];
        float4 g0 = *(const float4*)(gw + k * 8);
        float4 g1 = *(const float4*)(gw + k * 8 + 4);
        acc[0] += xv * g0.x; acc[1] += xv * g0.y;
        acc[2] += xv * g0.z; acc[3] += xv * g0.w;
        acc[4] += xv * g1.x; acc[5] += xv * g1.y;
        acc[6] += xv * g1.z; acc[7] += xv * g1.w;
    }
#pragma unroll
    for (int e = 0; e < 8; e++)
#pragma unroll
        for (int off = 16; off > 0; off >>= 1)
            acc[e] += __shfl_down_sync(0xffffffffu, acc[e], off);

    __shared__ float wpart[8][8];
    __shared__ float logits[8];
    __shared__ float sw[2];
    __shared__ int   si[2];
    const int warp = tid >> 5, lane = tid & 31;
    if (lane == 0)
#pragma unroll
        for (int e = 0; e < 8; e++) wpart[warp][e] = acc[e];
    __syncthreads();
    if (tid < 8) {
        float s = 0.0f;
#pragma unroll
        for (int w = 0; w < 8; w++) s += wpart[w][tid];
        logits[tid] = s;
    }
    __syncthreads();

    if (tid == 0) {
        int i0 = 0; float v0 = logits[0];
#pragma unroll
        for (int e = 1; e < 8; e++) if (logits[e] > v0) { v0 = logits[e]; i0 = e; }
        int i1 = -1; float v1 = -3.4e38f;
#pragma unroll
        for (int e = 0; e < 8; e++)
            if (e != i0 && logits[e] > v1) { v1 = logits[e]; i1 = e; }
        float ex  = expf(v1 - v0);
        float inv = 1.0f / (1.0f + ex);
        float w0 = inv, w1 = ex * inv;
        si[0] = i0; si[1] = i1; sw[0] = w0; sw[1] = w1;
        int p0 = atomicAdd(&g_cnt[i0], 1);
        g_tok[i0 * BQ + p0] = b; g_wt[i0 * BQ + p0] = w0;
        int p1 = atomicAdd(&g_cnt[i1], 1);
        g_tok[i1 * BQ + p1] = b; g_wt[i1 * BQ + p1] = w1;
    }
    __syncthreads();
    if (tid < 8) {
        float v = (tid == si[0]) ? sw[0] : ((tid == si[1]) ? sw[1] : 0.0f);
        gate_out[(size_t)b * 8 + tid] = v;
    }
}

// ---------------------------------------------------------------------------
// Kernel: round x to fp16
// ---------------------------------------------------------------------------
__global__ __launch_bounds__(256)
void convert_x_kernel(const float* __restrict__ x) {
    size_t i = ((size_t)blockIdx.x * 256 + threadIdx.x) * 4;
    float4 v = *(const float4*)(x + i);
    uint2 hp;
    hp.x = (uint32_t)__half_as_ushort(__float2half_rn(v.x))
         | ((uint32_t)__half_as_ushort(__float2half_rn(v.y)) << 16);
    hp.y = (uint32_t)__half_as_ushort(__float2half_rn(v.z))
         | ((uint32_t)__half_as_ushort(__float2half_rn(v.w)) << 16);
    *(uint2*)(g_xh + i) = hp;
}

// ---------------------------------------------------------------------------
// Kernel: transpose w1/w2 -> [e][n][k] fp16.  Tile 32k x 128n per block,
// float4 global reads, conflict-free padded SMEM (stride 133), 16-fp16
// packed uint4 writes.  grid (8, 32, 16), block (32, 8).
// ---------------------------------------------------------------------------
__global__ __launch_bounds__(256)
void convert_w_kernel(const float* __restrict__ w1,
                      const float* __restrict__ w2) {
    __shared__ float t[32][133];       // pad 5 -> gcd(5,32)=1, conflict-free cols
    const int z = blockIdx.z;
    const float* src = (z < 8 ? w1 : w2) + (size_t)(z & 7) * DIN * DEXP;
    __half* dh = (z < 8 ? g_w1h : g_w2h) + (size_t)(z & 7) * DIN * DEXP;
    const int n0 = blockIdx.x * 128, k0 = blockIdx.y * 32;
    const int tx = threadIdx.x, ty = threadIdx.y;
    const int tid = ty * 32 + tx;

    // load 32k x 128n with float4 (each thread: 4 rows x 4 n)
#pragma unroll
    for (int j = 0; j < 32; j += 8) {
        float4 v = *(const float4*)(src + (size_t)(k0 + ty + j) * DEXP + n0 + tx * 4);
        t[ty + j][tx * 4]     = v.x;
        t[ty + j][tx * 4 + 1] = v.y;
        t[ty + j][tx * 4 + 2] = v.z;
        t[ty + j][tx * 4 + 3] = v.w;
    }
    __syncthreads();

    // write transposed: thread -> (n_local = tid>>1, k half = (tid&1)*16)
    const int nl = tid >> 1, kh = (tid & 1) * 16;
    uint32_t pk[8];
#pragma unroll
    for (int q = 0; q < 8; ++q) {
        __half h0 = __float2half_rn(t[kh + 2 * q][nl]);
        __half h1 = __float2half_rn(t[kh + 2 * q + 1][nl]);
        pk[q] = (uint32_t)__half_as_ushort(h0)
              | ((uint32_t)__half_as_ushort(h1) << 16);
    }
    __half* dst = dh + (size_t)(n0 + nl) * DIN + k0 + kh;
    ((uint4*)dst)[0] = make_uint4(pk[0], pk[1], pk[2], pk[3]);
    ((uint4*)dst)[1] = make_uint4(pk[4], pk[5], pk[6], pk[7]);
}

// ---------------------------------------------------------------------------
// fp16 mma.sync GEMMs (R10-exact). 8 warps: warp m = wid>>2 (64 rows),
// warp n = wid&3 (32 cols), acc[4][4][4]. 2 CTAs/SM. Two barriers per chunk.
// grid: x = e*64 + m_tile (early exit), y = n_tile (8).
// ---------------------------------------------------------------------------
struct FragPtrs { const __half *ah, *bh; };

// 256 threads: thread -> row (tid>>1), 4 consecutive 16B segs ((tid&1)*4 ..)
__device__ __forceinline__ void load_stage(uint32_t st, const FragPtrs& p,
                                           int k0, uint32_t so, int cs0) {
#pragma unroll
    for (int j = 0; j < 4; ++j)
        CPASYNC(st + so + j * 16,         p.ah + k0 + (cs0 + j) * 8);
#pragma unroll
    for (int j = 0; j < 4; ++j)
        CPASYNC(st + ARR_B + so + j * 16, p.bh + k0 + (cs0 + j) * 8);
    CPCOMMIT();
}

__device__ __forceinline__ void compute_chunk(uint32_t st, uint32_t aoff,
                                              uint32_t boff, float acc[4][4][4]) {
#pragma unroll
    for (int kk = 0; kk < 4; ++kk) {
        uint32_t ah[4][4], bh[2][4];
#pragma unroll
        for (int i = 0; i < 4; ++i)
            ldm4(ah[i], st + aoff + i * (16 * ROWB) + kk * 32);
#pragma unroll
        for (int pp = 0; pp < 2; ++pp)
            ldm4(bh[pp], st + ARR_B + boff + pp * (16 * ROWB) + kk * 32);
#pragma unroll
        for (int i = 0; i < 4; ++i)
#pragma unroll
            for (int nt = 0; nt < 4; ++nt)
                mma_f16(acc[i][nt], ah[i], &bh[nt >> 1][(nt & 1) * 2]);
    }
}

__device__ __forceinline__ void run_mainloop(uint32_t sbase, const FragPtrs& p,
                                             uint32_t so, int cs0,
                                             uint32_t aoff, uint32_t boff,
                                             float acc[4][4][4]) {
#pragma unroll
    for (int s = 0; s < NSTAGE - 1; ++s)
        load_stage(sbase + s * STAGE_B, p, s * BK, so, cs0);
#pragma unroll 1
    for (int c = 0; c < NCHUNK; ++c) {
        if (c + NSTAGE - 1 < NCHUNK) CPWAIT1(); else CPWAIT0();
        __syncthreads();
        if (c + NSTAGE - 1 < NCHUNK)
            load_stage(sbase + ((c + NSTAGE - 1) % NSTAGE) * STAGE_B, p,
                       (c + NSTAGE - 1) * BK, so, cs0);
        compute_chunk(sbase + (c % NSTAGE) * STAGE_B, aoff, boff, acc);
        __syncthreads();
    }
}

__global__ __launch_bounds__(256, 2)
void gemm1_mma(const float* __restrict__ b1) {
    extern __shared__ char sm[];
    const int e    = blockIdx.x >> 6;
    const int tm   = blockIdx.x & 63;
    const int cnt  = g_cnt[e];
    const int row0 = tm * 128;
    if (row0 >= cnt) return;
    const int n0  = blockIdx.y * 128;
    const int tid = threadIdx.x;
    const int wid = tid >> 5, lane = tid & 31;
    const int wm = wid >> 2, wn = wid & 3;

    const uint32_t sbase = smem_u32(sm);
    int* tok_s = (int*)(sm + TOK_OFF);
    if (tid < 128) {
        int r = row0 + tid;
        tok_s[tid] = (r < cnt) ? g_tok[e * BQ + r] : g_tok[e * BQ + row0];
    }
    __syncthreads();

    const int crow = tid >> 1, cs0 = (tid & 1) * 4;
    const uint32_t so = crow * ROWB + cs0 * 16;
    FragPtrs p;
    p.ah = g_xh  + (size_t)tok_s[crow] * DIN;
    p.bh = g_w1h + ((size_t)e * DEXP + n0 + crow) * DIN;

    const uint32_t aoff = (wm * 64 + (lane & 15)) * ROWB + (lane >> 4) * 16;
    const uint32_t boff = (wn * 32 + ((lane >> 4) << 3) + (lane & 7)) * ROWB
                        + ((lane >> 3) & 1) * 16;

    float acc[4][4][4];
#pragma unroll
    for (int i = 0; i < 4; ++i)
#pragma unroll
        for (int j = 0; j < 4; ++j)
#pragma unroll
            for (int q = 0; q < 4; ++q) acc[i][j][q] = 0.0f;

    run_mainloop(sbase, p, so, cs0, aoff, boff, acc);

    // epilogue: bias + exact gelu -> fp16 h
    float bias[4][2];
#pragma unroll
    for (int nt = 0; nt < 4; ++nt) {
        int c0 = n0 + wn * 32 + nt * 8 + (lane & 3) * 2;
        bias[nt][0] = b1[e * DEXP + c0];
        bias[nt][1] = b1[e * DEXP + c0 + 1];
    }
#pragma unroll
    for (int i = 0; i < 4; ++i) {
#pragma unroll
        for (int half = 0; half < 2; ++half) {
            int r = wm * 64 + i * 16 + (lane >> 2) + half * 8;
            if (row0 + r >= cnt) continue;
            size_t rowbase = ((size_t)e * BQ + row0 + r) * DEXP;
#pragma unroll
            for (int nt = 0; nt < 4; ++nt) {
                int c0 = n0 + wn * 32 + nt * 8 + (lane & 3) * 2;
                float z0 = acc[i][nt][half * 2]     + bias[nt][0];
                float z1 = acc[i][nt][half * 2 + 1] + bias[nt][1];
                float gl0 = 0.5f * z0 * (1.0f + erff(z0 * 0.70710678118654752f));
                float gl1 = 0.5f * z1 * (1.0f + erff(z1 * 0.70710678118654752f));
                uint32_t hw = (uint32_t)__half_as_ushort(__float2half_rn(gl0))
                            | ((uint32_t)__half_as_ushort(__float2half_rn(gl1)) << 16);
                *(uint32_t*)(g_hh + rowbase + c0) = hw;
            }
        }
    }
}

__global__ __launch_bounds__(256, 2)
void gemm2_mma(const float* __restrict__ b2, float* __restrict__ out) {
    extern __shared__ char sm[];
    const int e    = blockIdx.x >> 6;
    const int tm   = blockIdx.x & 63;
    const int cnt  = g_cnt[e];
    const int row0 = tm * 128;
    if (row0 >= cnt) return;
    const int n0  = blockIdx.y * 128;
    const int tid = threadIdx.x;
    const int wid = tid >> 5, lane = tid & 31;
    const int wm = wid >> 2, wn = wid & 3;

    const uint32_t sbase = smem_u32(sm);
    int*   tok_s = (int*)(sm + TOK_OFF);
    float* wt_s  = (float*)(sm + TOK_OFF + 512);
    if (tid < 128) {
        int r = row0 + tid;
        if (r < cnt) { tok_s[tid] = g_tok[e * BQ + r]; wt_s[tid] = g_wt[e * BQ + r]; }
        else         { tok_s[tid] = 0;                 wt_s[tid] = 0.0f; }
    }
    __syncthreads();

    const int crow = tid >> 1, cs0 = (tid & 1) * 4;
    const uint32_t so = crow * ROWB + cs0 * 16;
    FragPtrs p;
    p.ah = g_hh  + ((size_t)e * BQ + row0 + crow) * DEXP;
    p.bh = g_w2h + ((size_t)e * DEXP + n0 + crow) * DEXP;

    const uint32_t aoff = (wm * 64 + (lane & 15)) * ROWB + (lane >> 4) * 16;
    const uint32_t boff = (wn * 32 + ((lane >> 4) << 3) + (lane & 7)) * ROWB
                        + ((lane >> 3) & 1) * 16;

    float acc[4][4][4];
#pragma unroll
    for (int i = 0; i < 4; ++i)
#pragma unroll
        for (int j = 0; j < 4; ++j)
#pragma unroll
            for (int q = 0; q < 4; ++q) acc[i][j][q] = 0.0f;

    run_mainloop(sbase, p, so, cs0, aoff, boff, acc);

    // epilogue: gate_w * (acc + bias) -> atomicAdd into out (2 deterministic
    // commutative fp32 adds per element onto zeroed buffer)
    float bias[4][2];
#pragma unroll
    for (int nt = 0; nt < 4; ++nt) {
        int c0 = n0 + wn * 32 + nt * 8 + (lane & 3) * 2;
        bias[nt][0] = b2[e * DEXP + c0];
        bias[nt][1] = b2[e * DEXP + c0 + 1];
    }
#pragma unroll
    for (int i = 0; i < 4; ++i) {
#pragma unroll
        for (int half = 0; half < 2; ++half) {
            int r = wm * 64 + i * 16 + (lane >> 2) + half * 8;
            if (row0 + r >= cnt) continue;
            float wgt = wt_s[r];
            float* orow = out + (size_t)tok_s[r] * DEXP;
#pragma unroll
            for (int nt = 0; nt < 4; ++nt) {
                int c0 = n0 + wn * 32 + nt * 8 + (lane & 3) * 2;
                atomicAdd(&orow[c0],     wgt * (acc[i][nt][half * 2]     + bias[nt][0]));
                atomicAdd(&orow[c0 + 1], wgt * (acc[i][nt][half * 2 + 1] + bias[nt][1]));
            }
        }
    }
}

// ---------------------------------------------------------------------------
// Launch: output = [moe_output (B*DEXP) | gate_weights (B*NEXP)]
// ---------------------------------------------------------------------------
extern "C" void kernel_launch(void* const* d_in, const int* in_sizes, int n_in,
                              void* d_out, int out_size) {
    const float* x  = (const float*)d_in[0];
    const float* gw = (const float*)d_in[1];
    const float* w1 = (const float*)d_in[2];
    const float* b1 = (const float*)d_in[3];
    const float* w2 = (const float*)d_in[4];
    const float* b2 = (const float*)d_in[5];
    float* out      = (float*)d_out;
    float* gate_out = out + (size_t)BQ * DEXP;

    cudaFuncSetAttribute(gemm1_mma, cudaFuncAttributeMaxDynamicSharedMemorySize, SMEM_T);
    cudaFuncSetAttribute(gemm2_mma, cudaFuncAttributeMaxDynamicSharedMemorySize, SMEM_T);

    init_kernel<<<(BQ * DEXP / 4 + 255) / 256, 256>>>(out);
    gate_kernel<<<BQ, 256>>>(x, gw, gate_out);
    convert_x_kernel<<<(BQ * DIN) / (256 * 4), 256>>>(x);
    convert_w_kernel<<<dim3(8, 32, 16), dim3(32, 8)>>>(w1, w2);

    dim3 grid(NEXP * (BQ / 128), DEXP / 128);
    gemm1_mma<<<grid, 256, SMEM_T>>>(b1);
    gemm2_mma<<<grid, 256, SMEM_T>>>(b2, out);
}